// round 1
// baseline (speedup 1.0000x reference)
#include <cuda_runtime.h>
#include <cuda_bf16.h>
#include <cstdint>

#define BINS 10
#define NBLOCKS 592
#define NTHREADS 256

__device__ double g_bce[BINS];
__device__ float  g_cnt[BINS];

__global__ void ghm_zero_kernel() {
    if (threadIdx.x < BINS) {
        g_bce[threadIdx.x] = 0.0;
        g_cnt[threadIdx.x] = 0.0f;
    }
}

__device__ __forceinline__ void proc_elem(float x, float t, float w,
                                          float* accb, float* accc) {
    // e = exp(-|x|); sigmoid via stable split; bce = max(x,0)+log(1+e)-x*t
    float e   = __expf(-fabsf(x));
    float ope = 1.0f + e;
    float inv = __fdividef(1.0f, ope);            // 1/(1+e)
    float s   = (x >= 0.0f) ? inv : (1.0f - inv); // sigmoid(x)
    float g   = fabsf(s - t);
    float bce = fmaxf(x, 0.0f) + __logf(ope) - x * t;

    int bin = (int)(g * (float)BINS);
    bin = min(bin, BINS - 1);

    float valid = (w > 0.0f) ? 1.0f : 0.0f;
    float bv = bce * valid;

#pragma unroll
    for (int b = 0; b < BINS; b++) {
        bool m = (bin == b);
        accb[b] += m ? bv : 0.0f;
        accc[b] += m ? valid : 0.0f;
    }
}

__global__ void __launch_bounds__(NTHREADS)
ghm_main_kernel(const float* __restrict__ pred,
                const float* __restrict__ target,
                const float* __restrict__ lw,
                int n) {
    float accb[BINS];
    float accc[BINS];
#pragma unroll
    for (int b = 0; b < BINS; b++) { accb[b] = 0.0f; accc[b] = 0.0f; }

    const int tid    = blockIdx.x * blockDim.x + threadIdx.x;
    const int stride = gridDim.x * blockDim.x;
    const int n4     = n >> 2;

    const float4* p4 = (const float4*)pred;
    const float4* t4 = (const float4*)target;
    const float4* w4 = (const float4*)lw;

    for (int i = tid; i < n4; i += stride) {
        float4 p = p4[i];
        float4 t = t4[i];
        float4 w = w4[i];
        proc_elem(p.x, t.x, w.x, accb, accc);
        proc_elem(p.y, t.y, w.y, accb, accc);
        proc_elem(p.z, t.z, w.z, accb, accc);
        proc_elem(p.w, t.w, w.w, accb, accc);
    }
    // scalar tail (n % 4)
    for (int i = (n4 << 2) + tid; i < n; i += stride) {
        proc_elem(pred[i], target[i], lw[i], accb, accc);
    }

    // warp reduction
    const int lane = threadIdx.x & 31;
#pragma unroll
    for (int b = 0; b < BINS; b++) {
        float vb = accb[b];
        float vc = accc[b];
#pragma unroll
        for (int o = 16; o > 0; o >>= 1) {
            vb += __shfl_down_sync(0xffffffffu, vb, o);
            vc += __shfl_down_sync(0xffffffffu, vc, o);
        }
        accb[b] = vb;
        accc[b] = vc;
    }

    __shared__ float s_b[BINS];
    __shared__ float s_c[BINS];
    if (threadIdx.x < BINS) { s_b[threadIdx.x] = 0.0f; s_c[threadIdx.x] = 0.0f; }
    __syncthreads();

    if (lane == 0) {
#pragma unroll
        for (int b = 0; b < BINS; b++) {
            atomicAdd(&s_b[b], accb[b]);
            atomicAdd(&s_c[b], accc[b]);
        }
    }
    __syncthreads();

    if (threadIdx.x < BINS) {
        atomicAdd(&g_bce[threadIdx.x], (double)s_b[threadIdx.x]);
        atomicAdd(&g_cnt[threadIdx.x], s_c[threadIdx.x]);
    }
}

__global__ void ghm_finalize_kernel(float* out) {
    if (threadIdx.x == 0) {
        double tot = 0.0;
        int n = 0;
        for (int b = 0; b < BINS; b++) {
            tot += (double)g_cnt[b];
            if (g_cnt[b] > 0.0f) n++;
        }
        double totm = tot > 1.0 ? tot : 1.0;
        double nm = (n > 1) ? (double)n : 1.0;
        double loss = 0.0;
        for (int b = 0; b < BINS; b++) {
            if (g_cnt[b] > 0.0f) {
                double w = (totm / (double)g_cnt[b]) / nm;
                loss += w * g_bce[b];
            }
        }
        loss /= totm;
        out[0] = (float)loss;  // LOSS_WEIGHT = 1.0
    }
}

extern "C" void kernel_launch(void* const* d_in, const int* in_sizes, int n_in,
                              void* d_out, int out_size) {
    const float* pred   = (const float*)d_in[0];
    const float* target = (const float*)d_in[1];
    const float* lw     = (const float*)d_in[2];
    // d_in[3] = bins (constant 10 per problem spec)
    float* out = (float*)d_out;
    int n = in_sizes[0];

    ghm_zero_kernel<<<1, 32>>>();
    ghm_main_kernel<<<NBLOCKS, NTHREADS>>>(pred, target, lw, n);
    ghm_finalize_kernel<<<1, 32>>>(out);
}

// round 2
// speedup vs baseline: 1.5525x; 1.5525x over previous
#include <cuda_runtime.h>
#include <cuda_bf16.h>
#include <cstdint>

#define BINS 10
#define NBLOCKS 592
#define NTHREADS 256
#define NWARPS (NTHREADS / 32)

__device__ double g_bce[BINS];   // zero-initialized at module load; finalize re-zeros
__device__ float  g_cnt[BINS];

// Packed (bce, count) per-lane shared histogram cell ops
__device__ __forceinline__ void proc(float x, float t, float w,
                                     unsigned long long* myhist) {
    // e = exp(-|x|)
    float e   = __expf(-fabsf(x));
    float ope = 1.0f + e;
    float inv = __fdividef(1.0f, ope);            // MUFU.RCP
    float s   = (x >= 0.0f) ? inv : (1.0f - inv); // sigmoid(x)
    float d   = s - t;
    float binf = fabsf(d) * (float)BINS;
    int bin = min((int)binf, BINS - 1);

    float lg  = __logf(ope);                      // log(1+e)
    float bce = fmaxf(x, 0.0f) + lg - x * t;

    bool valid = (w > 0.0f);
    float bv = valid ? bce : 0.0f;
    float cv = valid ? 1.0f : 0.0f;

    unsigned long long add;
    asm("mov.b64 %0, {%1, %2};" : "=l"(add) : "f"(bv), "f"(cv));

    unsigned long long* cell = myhist + (bin << 5);   // bin stride = 32 lanes
    unsigned long long old = *cell;
    unsigned long long nw;
    asm("add.rn.f32x2 %0, %1, %2;" : "=l"(nw) : "l"(old), "l"(add));
    *cell = nw;
}

__global__ void __launch_bounds__(NTHREADS)
ghm_main_kernel(const float* __restrict__ pred,
                const float* __restrict__ target,
                const float* __restrict__ lw,
                int n) {
    // [warp][bin][lane] packed (bce,count); lane-major rows -> conflict-free LDS.64/STS.64
    __shared__ unsigned long long hist[NWARPS][BINS][32];
    __shared__ float s_b[BINS];
    __shared__ float s_c[BINS];

    const int warp = threadIdx.x >> 5;
    const int lane = threadIdx.x & 31;

    // zero my lane's cells
#pragma unroll
    for (int b = 0; b < BINS; b++) hist[warp][b][lane] = 0ull;
    if (threadIdx.x < BINS) { s_b[threadIdx.x] = 0.0f; s_c[threadIdx.x] = 0.0f; }
    __syncthreads();

    unsigned long long* myhist = &hist[warp][0][lane];

    const int tid    = blockIdx.x * blockDim.x + threadIdx.x;
    const int stride = gridDim.x * blockDim.x;
    const int n4     = n >> 2;

    const float4* p4 = (const float4*)pred;
    const float4* t4 = (const float4*)target;
    const float4* w4 = (const float4*)lw;

    for (int i = tid; i < n4; i += stride) {
        float4 p = p4[i];
        float4 t = t4[i];
        float4 w = w4[i];
        proc(p.x, t.x, w.x, myhist);
        proc(p.y, t.y, w.y, myhist);
        proc(p.z, t.z, w.z, myhist);
        proc(p.w, t.w, w.w, myhist);
    }
    for (int i = (n4 << 2) + tid; i < n; i += stride) {
        proc(pred[i], target[i], lw[i], myhist);
    }
    __syncwarp();

    // per-warp reduce: each lane owns hist[warp][b][lane]
#pragma unroll
    for (int b = 0; b < BINS; b++) {
        unsigned long long v = hist[warp][b][lane];
        float vb, vc;
        asm("mov.b64 {%0, %1}, %2;" : "=f"(vb), "=f"(vc) : "l"(v));
#pragma unroll
        for (int o = 16; o > 0; o >>= 1) {
            vb += __shfl_down_sync(0xffffffffu, vb, o);
            vc += __shfl_down_sync(0xffffffffu, vc, o);
        }
        if (lane == 0) {
            atomicAdd(&s_b[b], vb);
            atomicAdd(&s_c[b], vc);
        }
    }
    __syncthreads();

    if (threadIdx.x < BINS) {
        atomicAdd(&g_bce[threadIdx.x], (double)s_b[threadIdx.x]);
        atomicAdd(&g_cnt[threadIdx.x], s_c[threadIdx.x]);
    }
}

__global__ void ghm_finalize_kernel(float* out) {
    if (threadIdx.x == 0) {
        double tot = 0.0;
        int nb = 0;
        for (int b = 0; b < BINS; b++) {
            tot += (double)g_cnt[b];
            if (g_cnt[b] > 0.0f) nb++;
        }
        double totm = tot > 1.0 ? tot : 1.0;
        double nm = (nb > 1) ? (double)nb : 1.0;
        double loss = 0.0;
        for (int b = 0; b < BINS; b++) {
            if (g_cnt[b] > 0.0f) {
                double w = (totm / (double)g_cnt[b]) / nm;
                loss += w * g_bce[b];
            }
        }
        loss /= totm;
        out[0] = (float)loss;  // LOSS_WEIGHT = 1.0

        // reset accumulators for the next (graph-replayed) call
        for (int b = 0; b < BINS; b++) { g_bce[b] = 0.0; g_cnt[b] = 0.0f; }
    }
}

extern "C" void kernel_launch(void* const* d_in, const int* in_sizes, int n_in,
                              void* d_out, int out_size) {
    const float* pred   = (const float*)d_in[0];
    const float* target = (const float*)d_in[1];
    const float* lw     = (const float*)d_in[2];
    float* out = (float*)d_out;
    int n = in_sizes[0];

    ghm_main_kernel<<<NBLOCKS, NTHREADS>>>(pred, target, lw, n);
    ghm_finalize_kernel<<<1, 32>>>(out);
}

// round 3
// speedup vs baseline: 1.6138x; 1.0395x over previous
#include <cuda_runtime.h>
#include <cuda_bf16.h>
#include <cstdint>

#define BINS 10
#define NBLOCKS 592
#define NTHREADS 256
#define NWARPS (NTHREADS / 32)

__device__ double g_bce[BINS];       // zero at load; last block resets each call
__device__ float  g_cnt[BINS];
__device__ unsigned int g_done = 0;

__device__ __forceinline__ void proc(float x, float t, float w,
                                     unsigned long long* myhist) {
    float e   = __expf(-fabsf(x));
    float ope = 1.0f + e;
    float inv = __fdividef(1.0f, ope);            // MUFU.RCP
    float s   = (x >= 0.0f) ? inv : (1.0f - inv); // sigmoid(x)
    float d   = s - t;
    float binf = fabsf(d) * (float)BINS;
    int bin = min((int)binf, BINS - 1);

    float lg  = __logf(ope);                      // log(1+e)
    float bce = fmaxf(x, 0.0f) + lg - x * t;

    bool valid = (w > 0.0f);
    float bv = valid ? bce : 0.0f;
    float cv = valid ? 1.0f : 0.0f;

    unsigned long long add;
    asm("mov.b64 %0, {%1, %2};" : "=l"(add) : "f"(bv), "f"(cv));

    unsigned long long* cell = myhist + (bin << 5);   // bin stride = 32 lanes
    unsigned long long old = *cell;
    unsigned long long nw;
    asm("add.rn.f32x2 %0, %1, %2;" : "=l"(nw) : "l"(old), "l"(add));
    *cell = nw;
}

__global__ void __launch_bounds__(NTHREADS)
ghm_fused_kernel(const float* __restrict__ pred,
                 const float* __restrict__ target,
                 const float* __restrict__ lw,
                 float* __restrict__ out,
                 int n) {
    __shared__ unsigned long long hist[NWARPS][BINS][32];
    __shared__ float s_b[BINS];
    __shared__ float s_c[BINS];
    __shared__ bool s_last;

    const int warp = threadIdx.x >> 5;
    const int lane = threadIdx.x & 31;

#pragma unroll
    for (int b = 0; b < BINS; b++) hist[warp][b][lane] = 0ull;
    if (threadIdx.x < BINS) { s_b[threadIdx.x] = 0.0f; s_c[threadIdx.x] = 0.0f; }
    __syncthreads();

    unsigned long long* myhist = &hist[warp][0][lane];

    const int tid    = blockIdx.x * blockDim.x + threadIdx.x;
    const int stride = gridDim.x * blockDim.x;
    const int n4     = n >> 2;

    const float4* p4 = (const float4*)pred;
    const float4* t4 = (const float4*)target;
    const float4* w4 = (const float4*)lw;

    int i = tid;
    // 2x-unrolled main loop: 6 LDG.128 front-batched for MLP
    for (; i + stride < n4; i += 2 * stride) {
        float4 pa = __ldcs(&p4[i]);
        float4 ta = __ldcs(&t4[i]);
        float4 wa = __ldcs(&w4[i]);
        float4 pb = __ldcs(&p4[i + stride]);
        float4 tb = __ldcs(&t4[i + stride]);
        float4 wb = __ldcs(&w4[i + stride]);
        proc(pa.x, ta.x, wa.x, myhist);
        proc(pa.y, ta.y, wa.y, myhist);
        proc(pa.z, ta.z, wa.z, myhist);
        proc(pa.w, ta.w, wa.w, myhist);
        proc(pb.x, tb.x, wb.x, myhist);
        proc(pb.y, tb.y, wb.y, myhist);
        proc(pb.z, tb.z, wb.z, myhist);
        proc(pb.w, tb.w, wb.w, myhist);
    }
    for (; i < n4; i += stride) {
        float4 p = __ldcs(&p4[i]);
        float4 t = __ldcs(&t4[i]);
        float4 w = __ldcs(&w4[i]);
        proc(p.x, t.x, w.x, myhist);
        proc(p.y, t.y, w.y, myhist);
        proc(p.z, t.z, w.z, myhist);
        proc(p.w, t.w, w.w, myhist);
    }
    for (int j = (n4 << 2) + tid; j < n; j += stride) {
        proc(pred[j], target[j], lw[j], myhist);
    }
    __syncwarp();

    // per-warp reduce: each lane owns hist[warp][b][lane]
#pragma unroll
    for (int b = 0; b < BINS; b++) {
        unsigned long long v = hist[warp][b][lane];
        float vb, vc;
        asm("mov.b64 {%0, %1}, %2;" : "=f"(vb), "=f"(vc) : "l"(v));
#pragma unroll
        for (int o = 16; o > 0; o >>= 1) {
            vb += __shfl_down_sync(0xffffffffu, vb, o);
            vc += __shfl_down_sync(0xffffffffu, vc, o);
        }
        if (lane == 0) {
            atomicAdd(&s_b[b], vb);
            atomicAdd(&s_c[b], vc);
        }
    }
    __syncthreads();

    if (threadIdx.x < BINS) {
        atomicAdd(&g_bce[threadIdx.x], (double)s_b[threadIdx.x]);
        atomicAdd(&g_cnt[threadIdx.x], s_c[threadIdx.x]);
    }

    // last-block finalize
    __threadfence();
    if (threadIdx.x == 0) {
        unsigned int v = atomicAdd(&g_done, 1u);
        s_last = (v == (unsigned int)(gridDim.x - 1));
    }
    __syncthreads();

    if (s_last && threadIdx.x == 0) {
        double tot = 0.0;
        int nb = 0;
        for (int b = 0; b < BINS; b++) {
            tot += (double)g_cnt[b];
            if (g_cnt[b] > 0.0f) nb++;
        }
        double totm = tot > 1.0 ? tot : 1.0;
        double nm = (nb > 1) ? (double)nb : 1.0;
        double loss = 0.0;
        for (int b = 0; b < BINS; b++) {
            if (g_cnt[b] > 0.0f) {
                double wpb = (totm / (double)g_cnt[b]) / nm;
                loss += wpb * g_bce[b];
            }
        }
        loss /= totm;
        out[0] = (float)loss;  // LOSS_WEIGHT = 1.0

        // reset for next graph replay (only this block is still active)
        for (int b = 0; b < BINS; b++) { g_bce[b] = 0.0; g_cnt[b] = 0.0f; }
        g_done = 0;
    }
}

extern "C" void kernel_launch(void* const* d_in, const int* in_sizes, int n_in,
                              void* d_out, int out_size) {
    const float* pred   = (const float*)d_in[0];
    const float* target = (const float*)d_in[1];
    const float* lw     = (const float*)d_in[2];
    float* out = (float*)d_out;
    int n = in_sizes[0];

    ghm_fused_kernel<<<NBLOCKS, NTHREADS>>>(pred, target, lw, out, n);
}